// round 16
// baseline (speedup 1.0000x reference)
#include <cuda_runtime.h>
#include <cuda_bf16.h>
#include <cstdint>
#include <cstddef>

static constexpr int B_ = 8192;
static constexpr int L_ = 2048;
static constexpr int NF_ = 8;

// GEMM tiling: CTA 64x128, K-chunk 32, 8 warps (2x4), warp tile 32x32,
// 3-stage cp.async pipeline, XOR-swizzled smem, 2 CTAs/SM.
// Grid = 2048 CTAs -> 6.92 waves over 296 slots (tail loss 1.2% vs 13.5%
// for the old 1024-CTA grid at 3.46 waves).
static constexpr int ROW_B    = 64;                    // 64B rows (32 bf16), XOR swizzle
static constexpr int A_TILE_B = 64 * ROW_B;            // 4096 B  (64 rows)
static constexpr int W_TILE_B = 128 * ROW_B;           // 8192 B  (128 rows)
static constexpr int STAGE_B  = 2 * A_TILE_B + 2 * W_TILE_B;  // 24576 B
static constexpr int NSTAGE   = 3;
static constexpr int GEMM_SMEM = NSTAGE * STAGE_B;     // 73728 B -> 2 CTAs/SM

// stage-internal offsets
static constexpr int OFF_AH = 0;
static constexpr int OFF_AL = A_TILE_B;                // 4096
static constexpr int OFF_WH = 2 * A_TILE_B;            // 8192
static constexpr int OFF_WL = 2 * A_TILE_B + W_TILE_B; // 16384

// XOR swizzle: 16B-column c in row r -> c ^ ((r>>1)&3). Conflict-free for
// ldmatrix reads and cp.async stores (bank bijection per 8-row phase).
__device__ __forceinline__ uint32_t sw_off(uint32_t row, uint32_t c16) {
    return row * ROW_B + ((c16 ^ ((row >> 1) & 3u)) << 4);
}

// ---------- device scratch (static; runtime alloc forbidden) ----------
__device__ __align__(256) __nv_bfloat16 g_Whi[(size_t)NF_ * L_ * L_];
__device__ __align__(256) __nv_bfloat16 g_Wlo[(size_t)NF_ * L_ * L_];
__device__ __align__(256) __nv_bfloat16 g_Xhi[2 * (size_t)B_ * L_];
__device__ __align__(256) __nv_bfloat16 g_Xlo[2 * (size_t)B_ * L_];
__device__ int g_dummy_sink;

// ---------- PTX helpers (sm_80+ portable only) ----------
__device__ __forceinline__ uint32_t smem_u32(const void* p) {
    uint32_t a;
    asm("{ .reg .u64 t; cvta.to.shared.u64 t, %1; cvt.u32.u64 %0, t; }" : "=r"(a) : "l"(p));
    return a;
}

__device__ __forceinline__ void cp16(uint32_t dst, const void* src) {
    asm volatile("cp.async.cg.shared.global [%0], [%1], 16;" :: "r"(dst), "l"(src));
}
#define CP_COMMIT() asm volatile("cp.async.commit_group;")
#define CP_WAIT1()  asm volatile("cp.async.wait_group 1;")

__device__ __forceinline__ void ldsm_x4(uint32_t& r0, uint32_t& r1, uint32_t& r2, uint32_t& r3,
                                        uint32_t addr) {
    asm volatile("ldmatrix.sync.aligned.m8n8.x4.shared.b16 {%0,%1,%2,%3}, [%4];"
                 : "=r"(r0), "=r"(r1), "=r"(r2), "=r"(r3) : "r"(addr));
}

__device__ __forceinline__ void mma_bf16(float* c, const uint32_t* a, const uint32_t* b) {
    asm volatile(
        "mma.sync.aligned.m16n8k16.row.col.f32.bf16.bf16.f32 "
        "{%0,%1,%2,%3}, {%4,%5,%6,%7}, {%8,%9}, {%0,%1,%2,%3};"
        : "+f"(c[0]), "+f"(c[1]), "+f"(c[2]), "+f"(c[3])
        : "r"(a[0]), "r"(a[1]), "r"(a[2]), "r"(a[3]), "r"(b[0]), "r"(b[1]));
}

// ---------- dummy kernel: keeps ncu -s 5 -c 1 capture window on hf_gemm ----------
__global__ void dummy_shift() {
    if (threadIdx.x == 0) g_dummy_sink = 1;
}

// ---------- GEMM: C[B,L]=(Ahi+Alo)@(Whi+Wlo)^T + bias, output split hi/lo ----------
__global__ void __launch_bounds__(256, 2)
hf_gemm(const __nv_bfloat16* __restrict__ Ahi, const __nv_bfloat16* __restrict__ Alo,
        const __nv_bfloat16* __restrict__ Whi, const __nv_bfloat16* __restrict__ Wlo,
        const float* __restrict__ bias,
        __nv_bfloat16* __restrict__ Chi, __nv_bfloat16* __restrict__ Clo)
{
    extern __shared__ char smem[];
    const uint32_t sbase = smem_u32(smem);

    const int tid = threadIdx.x;
    const int wid = tid >> 5;
    const int lid = tid & 31;
    const int wm  = wid & 1;      // M half:    rows wm*32 .. +32
    const int wn  = wid >> 1;     // N quarter: cols wn*32 .. +32

    const size_t m0 = (size_t)blockIdx.x * 64;
    const size_t n0 = (size_t)blockIdx.y * 128;

    // ldmatrix lane address components
    const uint32_t q  = (uint32_t)lid >> 3;
    const uint32_t rr = (uint32_t)lid & 7;
    const uint32_t a_lane_row = ((q & 1) << 3) + rr;   // + wm*32 + f*16
    const uint32_t a_lane_c   = q >> 1;                // 16B col within chunk (+ ks*2)
    const uint32_t b_lane_row = ((q >> 1) << 3) + rr;  // + wn*32 + p*16
    const uint32_t b_lane_c   = q & 1;

    // ---- async stage loader: (2*256 + 2*512) = 1536 16B-chunks / 256 thr = 6 each
    auto load_stage = [&](int stage, int kc) {
        const size_t k0 = (size_t)kc * 32;
        const uint32_t sb = sbase + (uint32_t)(stage * STAGE_B);
#pragma unroll
        for (int i = 0; i < 6; i++) {
            const int idx = tid + (i << 8);
            const __nv_bfloat16* src;
            size_t grow;
            uint32_t toff;
            int ch;
            if (i < 1)      { src = Ahi; ch = idx;        grow = m0 + (ch >> 2); toff = OFF_AH; }
            else if (i < 2) { src = Alo; ch = idx - 256;  grow = m0 + (ch >> 2); toff = OFF_AL; }
            else if (i < 4) { src = Whi; ch = idx - 512;  grow = n0 + (ch >> 2); toff = OFF_WH; }
            else            { src = Wlo; ch = idx - 1024; grow = n0 + (ch >> 2); toff = OFF_WL; }
            const uint32_t row = (uint32_t)(ch >> 2);
            const uint32_t cc  = (uint32_t)(ch & 3);
            const uint32_t dst = sb + toff + sw_off(row, cc);
            cp16(dst, src + grow * L_ + k0 + (size_t)cc * 8);
        }
    };

    float c[32];
#pragma unroll
    for (int i = 0; i < 32; i++) c[i] = 0.f;

    const int NK = L_ / 32;   // 64
    load_stage(0, 0); CP_COMMIT();
    load_stage(1, 1); CP_COMMIT();

#pragma unroll 1
    for (int kc = 0; kc < NK; ++kc) {
        CP_WAIT1();          // stage kc's group complete (<=1 group pending)
        __syncthreads();     // data visible; WAR guard for prefetch target

        const int ps = kc + 2;
        if (ps < NK) load_stage(ps % NSTAGE, ps);
        CP_COMMIT();

        const uint32_t ss = sbase + (uint32_t)((kc % NSTAGE) * STAGE_B);
#pragma unroll
        for (int ks = 0; ks < 2; ++ks) {
            uint32_t ah[2][4], al[2][4];
#pragma unroll
            for (int f = 0; f < 2; ++f) {
                const uint32_t rowA = (uint32_t)(wm * 32 + f * 16) + a_lane_row;
                const uint32_t c16  = (uint32_t)(ks * 2) + a_lane_c;
                ldsm_x4(ah[f][0], ah[f][1], ah[f][2], ah[f][3],
                        ss + OFF_AH + sw_off(rowA, c16));
                ldsm_x4(al[f][0], al[f][1], al[f][2], al[f][3],
                        ss + OFF_AL + sw_off(rowA, c16));
            }
            uint32_t bh[8], bl[8];
#pragma unroll
            for (int p = 0; p < 2; ++p) {
                const uint32_t rowB = (uint32_t)(wn * 32 + p * 16) + b_lane_row;
                const uint32_t c16  = (uint32_t)(ks * 2) + b_lane_c;
                ldsm_x4(bh[4 * p + 0], bh[4 * p + 1], bh[4 * p + 2], bh[4 * p + 3],
                        ss + OFF_WH + sw_off(rowB, c16));
                ldsm_x4(bl[4 * p + 0], bl[4 * p + 1], bl[4 * p + 2], bl[4 * p + 3],
                        ss + OFF_WL + sw_off(rowB, c16));
            }
            // product-major: each pass = 8 independent accumulators
#pragma unroll
            for (int f = 0; f < 2; ++f)
#pragma unroll
                for (int j = 0; j < 4; ++j)
                    mma_bf16(&c[(f * 4 + j) * 4], ah[f], &bh[2 * j]);   // hi*hi
#pragma unroll
            for (int f = 0; f < 2; ++f)
#pragma unroll
                for (int j = 0; j < 4; ++j)
                    mma_bf16(&c[(f * 4 + j) * 4], ah[f], &bl[2 * j]);   // hi*lo
#pragma unroll
            for (int f = 0; f < 2; ++f)
#pragma unroll
                for (int j = 0; j < 4; ++j)
                    mma_bf16(&c[(f * 4 + j) * 4], al[f], &bh[2 * j]);   // lo*hi
        }
    }

    // ---- epilogue: bias + hi/lo split, straight from fragments ----
    const int g = lid >> 2;
    const int t = lid & 3;
#pragma unroll
    for (int j = 0; j < 4; ++j) {
        const size_t col = n0 + (size_t)(wn * 32 + j * 8 + 2 * t);
        const float b0v = __ldg(bias + col);
        const float b1v = __ldg(bias + col + 1);
#pragma unroll
        for (int f = 0; f < 2; ++f) {
            const size_t r0 = m0 + (size_t)(wm * 32 + f * 16 + g);
            const float* cf = &c[(f * 4 + j) * 4];
#pragma unroll
            for (int h = 0; h < 2; ++h) {
                const float f0 = cf[2 * h + 0] + b0v;
                const float f1 = cf[2 * h + 1] + b1v;
                __nv_bfloat162 h2 = __floats2bfloat162_rn(f0, f1);
                const float l0 = f0 - __bfloat162float(h2.x);
                const float l1 = f1 - __bfloat162float(h2.y);
                __nv_bfloat162 l2 = __floats2bfloat162_rn(l0, l1);
                const size_t off = (r0 + (size_t)(8 * h)) * L_ + col;
                *reinterpret_cast<uint32_t*>(Chi + off) = *reinterpret_cast<uint32_t*>(&h2);
                *reinterpret_cast<uint32_t*>(Clo + off) = *reinterpret_cast<uint32_t*>(&l2);
            }
        }
    }
}

// ---------- Householder flow: z -= 2 v (v.z)/||v||^2, one block per batch row ----------
__global__ void __launch_bounds__(256) hf_flow(
    const __nv_bfloat16* __restrict__ Vhi, const __nv_bfloat16* __restrict__ Vlo,
    float* __restrict__ Z)
{
    __shared__ float rvz[8], rnn[8];
    __shared__ float s_coef;
    const int tid = threadIdx.x;
    const size_t base = (size_t)blockIdx.x * L_ + (size_t)tid * 8;

    uint4 h4 = *reinterpret_cast<const uint4*>(Vhi + base);
    uint4 l4 = *reinterpret_cast<const uint4*>(Vlo + base);
    float4 za = *reinterpret_cast<const float4*>(Z + base);
    float4 zb = *reinterpret_cast<const float4*>(Z + base + 4);

    float v[8], z[8];
    {
        const uint32_t* hp = &h4.x;
        const uint32_t* lp = &l4.x;
#pragma unroll
        for (int qq = 0; qq < 4; qq++) {
            float2 h = __bfloat1622float2(*reinterpret_cast<const __nv_bfloat162*>(&hp[qq]));
            float2 l = __bfloat1622float2(*reinterpret_cast<const __nv_bfloat162*>(&lp[qq]));
            v[2 * qq]     = h.x + l.x;
            v[2 * qq + 1] = h.y + l.y;
        }
    }
    z[0] = za.x; z[1] = za.y; z[2] = za.z; z[3] = za.w;
    z[4] = zb.x; z[5] = zb.y; z[6] = zb.z; z[7] = zb.w;

    float vz = 0.f, nn = 0.f;
#pragma unroll
    for (int i = 0; i < 8; i++) { vz += v[i] * z[i]; nn += v[i] * v[i]; }
#pragma unroll
    for (int o = 16; o > 0; o >>= 1) {
        vz += __shfl_xor_sync(0xFFFFFFFFu, vz, o);
        nn += __shfl_xor_sync(0xFFFFFFFFu, nn, o);
    }
    if ((tid & 31) == 0) { rvz[tid >> 5] = vz; rnn[tid >> 5] = nn; }
    __syncthreads();
    if (tid == 0) {
        float a = 0.f, b = 0.f;
#pragma unroll
        for (int i = 0; i < 8; i++) { a += rvz[i]; b += rnn[i]; }
        s_coef = 2.0f * a / b;
    }
    __syncthreads();
    const float cf = s_coef;
#pragma unroll
    for (int i = 0; i < 8; i++) z[i] -= cf * v[i];

    *reinterpret_cast<float4*>(Z + base)     = make_float4(z[0], z[1], z[2], z[3]);
    *reinterpret_cast<float4*>(Z + base + 4) = make_float4(z[4], z[5], z[6], z[7]);
}

// ---------- splitters: fp32 -> bf16 hi + bf16 lo ----------
__device__ __forceinline__ void split4(float4 v, uint2& h, uint2& l) {
    __nv_bfloat162 h0 = __floats2bfloat162_rn(v.x, v.y);
    __nv_bfloat162 h1 = __floats2bfloat162_rn(v.z, v.w);
    float lx = v.x - __bfloat162float(h0.x);
    float ly = v.y - __bfloat162float(h0.y);
    float lz = v.z - __bfloat162float(h1.x);
    float lw = v.w - __bfloat162float(h1.y);
    __nv_bfloat162 l0 = __floats2bfloat162_rn(lx, ly);
    __nv_bfloat162 l1 = __floats2bfloat162_rn(lz, lw);
    h.x = *reinterpret_cast<uint32_t*>(&h0);
    h.y = *reinterpret_cast<uint32_t*>(&h1);
    l.x = *reinterpret_cast<uint32_t*>(&l0);
    l.y = *reinterpret_cast<uint32_t*>(&l1);
}

__global__ void __launch_bounds__(256) split_w_kernel(
    const float* __restrict__ W0, const float* __restrict__ Ws,
    __nv_bfloat16* __restrict__ hi, __nv_bfloat16* __restrict__ lo)
{
    const size_t LL2 = (size_t)L_ * L_;
    size_t i = (size_t)blockIdx.x * blockDim.x + threadIdx.x;   // float4 index
    size_t e = i * 4;
    if (e >= (size_t)NF_ * LL2) return;
    float4 v = (e < LL2)
        ? reinterpret_cast<const float4*>(W0)[i]
        : reinterpret_cast<const float4*>(Ws)[i - LL2 / 4];
    uint2 h, l;
    split4(v, h, l);
    reinterpret_cast<uint2*>(hi)[i] = h;
    reinterpret_cast<uint2*>(lo)[i] = l;
}

__global__ void __launch_bounds__(256) split_x_kernel(
    const float* __restrict__ X,
    __nv_bfloat16* __restrict__ hi, __nv_bfloat16* __restrict__ lo)
{
    size_t i = (size_t)blockIdx.x * blockDim.x + threadIdx.x;
    if (i * 4 >= (size_t)B_ * L_) return;
    float4 v = reinterpret_cast<const float4*>(X)[i];
    uint2 h, l;
    split4(v, h, l);
    reinterpret_cast<uint2*>(hi)[i] = h;
    reinterpret_cast<uint2*>(lo)[i] = l;
}

// ---------- host ----------
extern "C" void kernel_launch(void* const* d_in, const int* in_sizes, int n_in,
                              void* d_out, int out_size)
{
    const float* z      = (const float*)d_in[0];
    const float* h_last = (const float*)d_in[1];
    const float* W0     = (const float*)d_in[2];
    const float* b0     = (const float*)d_in[3];
    const float* Ws     = (const float*)d_in[4];
    const float* bs     = (const float*)d_in[5];
    float* out = (float*)d_out;

    void *pWhi, *pWlo, *pXhi, *pXlo;
    cudaGetSymbolAddress(&pWhi, g_Whi);
    cudaGetSymbolAddress(&pWlo, g_Wlo);
    cudaGetSymbolAddress(&pXhi, g_Xhi);
    cudaGetSymbolAddress(&pXlo, g_Xlo);
    __nv_bfloat16* Whi = (__nv_bfloat16*)pWhi;
    __nv_bfloat16* Wlo = (__nv_bfloat16*)pWlo;
    __nv_bfloat16* Xhi = (__nv_bfloat16*)pXhi;
    __nv_bfloat16* Xlo = (__nv_bfloat16*)pXlo;

    cudaFuncSetAttribute(hf_gemm, cudaFuncAttributeMaxDynamicSharedMemorySize, GEMM_SMEM);

    const size_t LL2 = (size_t)L_ * L_;
    const size_t BL  = (size_t)B_ * L_;

    // 1) split weights (all 8 flows) into bf16 hi/lo           [launch 1]
    {
        size_t n4 = (size_t)NF_ * LL2 / 4;
        split_w_kernel<<<(unsigned)((n4 + 255) / 256), 256>>>(W0, Ws, Whi, Wlo);
    }
    // 2) split h_last into X buffer 0                          [launch 2]
    {
        size_t n4 = BL / 4;
        split_x_kernel<<<(unsigned)((n4 + 255) / 256), 256>>>(h_last, Xhi, Xlo);
    }
    // 3) keep ncu's -s 5 -c 1 window on hf_gemm                [launch 3]
    dummy_shift<<<1, 32>>>();

    // 4) z -> out (flows update in place)
    cudaMemcpyAsync(out, z, BL * sizeof(float), cudaMemcpyDeviceToDevice);

    // 5) chain: GEMM_j (src buf j&1 -> dst buf (j+1)&1), then flow_j on dst
    //    launches: gemm(4), flow(5), gemm(6) <- ncu profiles this one
    dim3 ggrid(B_ / 64, L_ / 128, 1);  // (128, 16) = 2048 CTAs
    for (int j = 0; j < NF_; j++) {
        const int sb = j & 1;
        const int db = (j + 1) & 1;
        const float* bias = (j == 0) ? b0 : (bs + (size_t)(j - 1) * L_);
        hf_gemm<<<ggrid, 256, GEMM_SMEM>>>(
            Xhi + (size_t)sb * BL, Xlo + (size_t)sb * BL,
            Whi + (size_t)j * LL2, Wlo + (size_t)j * LL2,
            bias,
            Xhi + (size_t)db * BL, Xlo + (size_t)db * BL);
        hf_flow<<<B_, 256>>>(Xhi + (size_t)db * BL, Xlo + (size_t)db * BL, out);
    }
}

// round 17
// speedup vs baseline: 1.0735x; 1.0735x over previous
#include <cuda_runtime.h>
#include <cuda_bf16.h>
#include <cstdint>
#include <cstddef>

static constexpr int B_ = 8192;
static constexpr int L_ = 2048;
static constexpr int NF_ = 8;

// GEMM tiling (R13 best): CTA 128x128, K-chunk 32, 8 warps (4x2), warp tile
// 32x64, 3-stage cp.async pipeline, XOR-swizzled smem, 2 CTAs/SM.
static constexpr int ROW_B    = 64;                    // 64B rows (32 bf16), XOR swizzle
static constexpr int T_TILE_B = 128 * ROW_B;           // 8192 B
static constexpr int STAGE_B  = 4 * T_TILE_B;          // 32768 B (Ah, Al, Wh, Wl)
static constexpr int NSTAGE   = 3;
static constexpr int GEMM_SMEM = NSTAGE * STAGE_B;     // 98304 B -> 2 CTAs/SM

// stage-internal offsets
static constexpr int OFF_AH = 0;
static constexpr int OFF_AL = 1 * T_TILE_B;
static constexpr int OFF_WH = 2 * T_TILE_B;
static constexpr int OFF_WL = 3 * T_TILE_B;

// XOR swizzle: 16B-column c in row r -> c ^ ((r>>1)&3). Conflict-free for
// ldmatrix reads and cp.async stores (bank bijection per 8-row phase).
__device__ __forceinline__ uint32_t sw_off(uint32_t row, uint32_t c16) {
    return row * ROW_B + ((c16 ^ ((row >> 1) & 3u)) << 4);
}

// ---------- device scratch (static; runtime alloc forbidden) ----------
__device__ __align__(256) __nv_bfloat16 g_Whi[(size_t)NF_ * L_ * L_];
__device__ __align__(256) __nv_bfloat16 g_Wlo[(size_t)NF_ * L_ * L_];
__device__ __align__(256) __nv_bfloat16 g_Xhi[2 * (size_t)B_ * L_];
__device__ __align__(256) __nv_bfloat16 g_Xlo[2 * (size_t)B_ * L_];
__device__ int g_dummy_sink;

// ---------- PTX helpers (sm_80+ portable only) ----------
__device__ __forceinline__ uint32_t smem_u32(const void* p) {
    uint32_t a;
    asm("{ .reg .u64 t; cvta.to.shared.u64 t, %1; cvt.u32.u64 %0, t; }" : "=r"(a) : "l"(p));
    return a;
}

__device__ __forceinline__ void cp16(uint32_t dst, const void* src) {
    asm volatile("cp.async.cg.shared.global [%0], [%1], 16;" :: "r"(dst), "l"(src));
}
#define CP_COMMIT() asm volatile("cp.async.commit_group;")
#define CP_WAIT1()  asm volatile("cp.async.wait_group 1;")

__device__ __forceinline__ void ldsm_x4(uint32_t& r0, uint32_t& r1, uint32_t& r2, uint32_t& r3,
                                        uint32_t addr) {
    asm volatile("ldmatrix.sync.aligned.m8n8.x4.shared.b16 {%0,%1,%2,%3}, [%4];"
                 : "=r"(r0), "=r"(r1), "=r"(r2), "=r"(r3) : "r"(addr));
}

__device__ __forceinline__ void mma_bf16(float* c, const uint32_t* a, const uint32_t* b) {
    asm volatile(
        "mma.sync.aligned.m16n8k16.row.col.f32.bf16.bf16.f32 "
        "{%0,%1,%2,%3}, {%4,%5,%6,%7}, {%8,%9}, {%0,%1,%2,%3};"
        : "+f"(c[0]), "+f"(c[1]), "+f"(c[2]), "+f"(c[3])
        : "r"(a[0]), "r"(a[1]), "r"(a[2]), "r"(a[3]), "r"(b[0]), "r"(b[1]));
}

// ---------- dummy kernel: keeps ncu -s 5 -c 1 capture window on hf_gemm ----------
__global__ void dummy_shift() {
    if (threadIdx.x == 0) g_dummy_sink = 1;
}

// ---------- GEMM: C[B,L]=(Ahi+Alo)@(Whi+Wlo)^T + bias, output split hi/lo ----------
__global__ void __launch_bounds__(256, 2)
hf_gemm(const __nv_bfloat16* __restrict__ Ahi, const __nv_bfloat16* __restrict__ Alo,
        const __nv_bfloat16* __restrict__ Whi, const __nv_bfloat16* __restrict__ Wlo,
        const float* __restrict__ bias,
        __nv_bfloat16* __restrict__ Chi, __nv_bfloat16* __restrict__ Clo)
{
    extern __shared__ char smem[];
    const uint32_t sbase = smem_u32(smem);

    const int tid = threadIdx.x;
    const int wid = tid >> 5;
    const int lid = tid & 31;
    const int wm  = wid & 3;      // M quarter: rows wm*32 .. +32
    const int wn  = wid >> 2;     // N half:    cols wn*64 .. +64

    const size_t m0 = (size_t)blockIdx.x * 128;
    const size_t n0 = (size_t)blockIdx.y * 128;

    // ldmatrix lane address components
    const uint32_t q  = (uint32_t)lid >> 3;
    const uint32_t rr = (uint32_t)lid & 7;
    const uint32_t a_lane_row = ((q & 1) << 3) + rr;   // + wm*32 + f*16
    const uint32_t a_lane_c   = q >> 1;                // 16B col within chunk (+ ks*2)
    const uint32_t b_lane_row = ((q >> 1) << 3) + rr;  // + wn*64 + p*16
    const uint32_t b_lane_c   = q & 1;

    // ---- async stage loader: 4 tiles x 512 16B-chunks = 2048 / 256 threads = 8 each
    auto load_stage = [&](int stage, int kc) {
        const size_t k0 = (size_t)kc * 32;
        const uint32_t sb = sbase + (uint32_t)(stage * STAGE_B);
#pragma unroll
        for (int i = 0; i < 8; i++) {
            const int idx = tid + (i << 8);
            const int ch  = idx & 511;           // chunk within tile
            const uint32_t row = (uint32_t)(ch >> 2);
            const uint32_t cc  = (uint32_t)(ch & 3);
            const __nv_bfloat16* src;
            size_t grow;
            uint32_t toff;
            if (i < 2)      { src = Ahi; grow = m0 + row; toff = OFF_AH; }
            else if (i < 4) { src = Alo; grow = m0 + row; toff = OFF_AL; }
            else if (i < 6) { src = Whi; grow = n0 + row; toff = OFF_WH; }
            else            { src = Wlo; grow = n0 + row; toff = OFF_WL; }
            const uint32_t dst = sb + toff + sw_off(row, cc);
            cp16(dst, src + grow * L_ + k0 + (size_t)cc * 8);
        }
    };

    float c[64];
#pragma unroll
    for (int i = 0; i < 64; i++) c[i] = 0.f;

    const int NK = L_ / 32;   // 64
    load_stage(0, 0); CP_COMMIT();
    load_stage(1, 1); CP_COMMIT();

#pragma unroll 1
    for (int kc = 0; kc < NK; ++kc) {
        CP_WAIT1();          // stage kc's group complete (<=1 group pending)
        __syncthreads();     // data visible; WAR guard for prefetch target

        const int ps = kc + 2;
        if (ps < NK) load_stage(ps % NSTAGE, ps);
        CP_COMMIT();

        const uint32_t ss = sbase + (uint32_t)((kc % NSTAGE) * STAGE_B);
#pragma unroll
        for (int ks = 0; ks < 2; ++ks) {
            uint32_t ah[2][4], al[2][4];
#pragma unroll
            for (int f = 0; f < 2; ++f) {
                const uint32_t rowA = (uint32_t)(wm * 32 + f * 16) + a_lane_row;
                const uint32_t c16  = (uint32_t)(ks * 2) + a_lane_c;
                ldsm_x4(ah[f][0], ah[f][1], ah[f][2], ah[f][3],
                        ss + OFF_AH + sw_off(rowA, c16));
                ldsm_x4(al[f][0], al[f][1], al[f][2], al[f][3],
                        ss + OFF_AL + sw_off(rowA, c16));
            }
            // process B in two halves of 4 j-columns -> halves live registers
#pragma unroll
            for (int h2 = 0; h2 < 2; ++h2) {
                uint32_t bh[8], bl[8];
#pragma unroll
                for (int p = 0; p < 2; ++p) {
                    const int pp = h2 * 2 + p;
                    const uint32_t rowB = (uint32_t)(wn * 64 + pp * 16) + b_lane_row;
                    const uint32_t c16  = (uint32_t)(ks * 2) + b_lane_c;
                    ldsm_x4(bh[4 * p + 0], bh[4 * p + 1], bh[4 * p + 2], bh[4 * p + 3],
                            ss + OFF_WH + sw_off(rowB, c16));
                    ldsm_x4(bl[4 * p + 0], bl[4 * p + 1], bl[4 * p + 2], bl[4 * p + 3],
                            ss + OFF_WL + sw_off(rowB, c16));
                }
                // product-major: each pass = 8 independent accumulators
#pragma unroll
                for (int f = 0; f < 2; ++f)
#pragma unroll
                    for (int j = 0; j < 4; ++j)
                        mma_bf16(&c[(f * 8 + h2 * 4 + j) * 4], ah[f], &bh[2 * j]);  // hi*hi
#pragma unroll
                for (int f = 0; f < 2; ++f)
#pragma unroll
                    for (int j = 0; j < 4; ++j)
                        mma_bf16(&c[(f * 8 + h2 * 4 + j) * 4], ah[f], &bl[2 * j]);  // hi*lo
#pragma unroll
                for (int f = 0; f < 2; ++f)
#pragma unroll
                    for (int j = 0; j < 4; ++j)
                        mma_bf16(&c[(f * 8 + h2 * 4 + j) * 4], al[f], &bh[2 * j]);  // lo*hi
            }
        }
    }

    // ---- epilogue: bias + hi/lo split, straight from fragments ----
    const int g = lid >> 2;
    const int t = lid & 3;
#pragma unroll
    for (int j = 0; j < 8; ++j) {
        const size_t col = n0 + (size_t)(wn * 64 + j * 8 + 2 * t);
        const float b0v = __ldg(bias + col);
        const float b1v = __ldg(bias + col + 1);
#pragma unroll
        for (int f = 0; f < 2; ++f) {
            const size_t r0 = m0 + (size_t)(wm * 32 + f * 16 + g);
            const float* cf = &c[(f * 8 + j) * 4];
#pragma unroll
            for (int h = 0; h < 2; ++h) {
                const float f0 = cf[2 * h + 0] + b0v;
                const float f1 = cf[2 * h + 1] + b1v;
                __nv_bfloat162 h2 = __floats2bfloat162_rn(f0, f1);
                const float l0 = f0 - __bfloat162float(h2.x);
                const float l1 = f1 - __bfloat162float(h2.y);
                __nv_bfloat162 l2 = __floats2bfloat162_rn(l0, l1);
                const size_t off = (r0 + (size_t)(8 * h)) * L_ + col;
                *reinterpret_cast<uint32_t*>(Chi + off) = *reinterpret_cast<uint32_t*>(&h2);
                *reinterpret_cast<uint32_t*>(Clo + off) = *reinterpret_cast<uint32_t*>(&l2);
            }
        }
    }
}

// ---------- Householder flow: z -= 2 v (v.z)/||v||^2, one block per batch row ----------
__global__ void __launch_bounds__(256) hf_flow(
    const __nv_bfloat16* __restrict__ Vhi, const __nv_bfloat16* __restrict__ Vlo,
    float* __restrict__ Z)
{
    __shared__ float rvz[8], rnn[8];
    __shared__ float s_coef;
    const int tid = threadIdx.x;
    const size_t base = (size_t)blockIdx.x * L_ + (size_t)tid * 8;

    uint4 h4 = *reinterpret_cast<const uint4*>(Vhi + base);
    uint4 l4 = *reinterpret_cast<const uint4*>(Vlo + base);
    float4 za = *reinterpret_cast<const float4*>(Z + base);
    float4 zb = *reinterpret_cast<const float4*>(Z + base + 4);

    float v[8], z[8];
    {
        const uint32_t* hp = &h4.x;
        const uint32_t* lp = &l4.x;
#pragma unroll
        for (int qq = 0; qq < 4; qq++) {
            float2 h = __bfloat1622float2(*reinterpret_cast<const __nv_bfloat162*>(&hp[qq]));
            float2 l = __bfloat1622float2(*reinterpret_cast<const __nv_bfloat162*>(&lp[qq]));
            v[2 * qq]     = h.x + l.x;
            v[2 * qq + 1] = h.y + l.y;
        }
    }
    z[0] = za.x; z[1] = za.y; z[2] = za.z; z[3] = za.w;
    z[4] = zb.x; z[5] = zb.y; z[6] = zb.z; z[7] = zb.w;

    float vz = 0.f, nn = 0.f;
#pragma unroll
    for (int i = 0; i < 8; i++) { vz += v[i] * z[i]; nn += v[i] * v[i]; }
#pragma unroll
    for (int o = 16; o > 0; o >>= 1) {
        vz += __shfl_xor_sync(0xFFFFFFFFu, vz, o);
        nn += __shfl_xor_sync(0xFFFFFFFFu, nn, o);
    }
    if ((tid & 31) == 0) { rvz[tid >> 5] = vz; rnn[tid >> 5] = nn; }
    __syncthreads();
    if (tid == 0) {
        float a = 0.f, b = 0.f;
#pragma unroll
        for (int i = 0; i < 8; i++) { a += rvz[i]; b += rnn[i]; }
        s_coef = 2.0f * a / b;
    }
    __syncthreads();
    const float cf = s_coef;
#pragma unroll
    for (int i = 0; i < 8; i++) z[i] -= cf * v[i];

    *reinterpret_cast<float4*>(Z + base)     = make_float4(z[0], z[1], z[2], z[3]);
    *reinterpret_cast<float4*>(Z + base + 4) = make_float4(z[4], z[5], z[6], z[7]);
}

// ---------- splitters: fp32 -> bf16 hi + bf16 lo ----------
__device__ __forceinline__ void split4(float4 v, uint2& h, uint2& l) {
    __nv_bfloat162 h0 = __floats2bfloat162_rn(v.x, v.y);
    __nv_bfloat162 h1 = __floats2bfloat162_rn(v.z, v.w);
    float lx = v.x - __bfloat162float(h0.x);
    float ly = v.y - __bfloat162float(h0.y);
    float lz = v.z - __bfloat162float(h1.x);
    float lw = v.w - __bfloat162float(h1.y);
    __nv_bfloat162 l0 = __floats2bfloat162_rn(lx, ly);
    __nv_bfloat162 l1 = __floats2bfloat162_rn(lz, lw);
    h.x = *reinterpret_cast<uint32_t*>(&h0);
    h.y = *reinterpret_cast<uint32_t*>(&h1);
    l.x = *reinterpret_cast<uint32_t*>(&l0);
    l.y = *reinterpret_cast<uint32_t*>(&l1);
}

__global__ void __launch_bounds__(256) split_w_kernel(
    const float* __restrict__ W0, const float* __restrict__ Ws,
    __nv_bfloat16* __restrict__ hi, __nv_bfloat16* __restrict__ lo)
{
    const size_t LL2 = (size_t)L_ * L_;
    size_t i = (size_t)blockIdx.x * blockDim.x + threadIdx.x;   // float4 index
    size_t e = i * 4;
    if (e >= (size_t)NF_ * LL2) return;
    float4 v = (e < LL2)
        ? reinterpret_cast<const float4*>(W0)[i]
        : reinterpret_cast<const float4*>(Ws)[i - LL2 / 4];
    uint2 h, l;
    split4(v, h, l);
    reinterpret_cast<uint2*>(hi)[i] = h;
    reinterpret_cast<uint2*>(lo)[i] = l;
}

__global__ void __launch_bounds__(256) split_x_kernel(
    const float* __restrict__ X,
    __nv_bfloat16* __restrict__ hi, __nv_bfloat16* __restrict__ lo)
{
    size_t i = (size_t)blockIdx.x * blockDim.x + threadIdx.x;
    if (i * 4 >= (size_t)B_ * L_) return;
    float4 v = reinterpret_cast<const float4*>(X)[i];
    uint2 h, l;
    split4(v, h, l);
    reinterpret_cast<uint2*>(hi)[i] = h;
    reinterpret_cast<uint2*>(lo)[i] = l;
}

// ---------- host ----------
extern "C" void kernel_launch(void* const* d_in, const int* in_sizes, int n_in,
                              void* d_out, int out_size)
{
    const float* z      = (const float*)d_in[0];
    const float* h_last = (const float*)d_in[1];
    const float* W0     = (const float*)d_in[2];
    const float* b0     = (const float*)d_in[3];
    const float* Ws     = (const float*)d_in[4];
    const float* bs     = (const float*)d_in[5];
    float* out = (float*)d_out;

    void *pWhi, *pWlo, *pXhi, *pXlo;
    cudaGetSymbolAddress(&pWhi, g_Whi);
    cudaGetSymbolAddress(&pWlo, g_Wlo);
    cudaGetSymbolAddress(&pXhi, g_Xhi);
    cudaGetSymbolAddress(&pXlo, g_Xlo);
    __nv_bfloat16* Whi = (__nv_bfloat16*)pWhi;
    __nv_bfloat16* Wlo = (__nv_bfloat16*)pWlo;
    __nv_bfloat16* Xhi = (__nv_bfloat16*)pXhi;
    __nv_bfloat16* Xlo = (__nv_bfloat16*)pXlo;

    cudaFuncSetAttribute(hf_gemm, cudaFuncAttributeMaxDynamicSharedMemorySize, GEMM_SMEM);

    const size_t LL2 = (size_t)L_ * L_;
    const size_t BL  = (size_t)B_ * L_;

    // second stream + events for flow/GEMM overlap (capture-legal fork/join)
    cudaStream_t s2;
    cudaStreamCreateWithFlags(&s2, cudaStreamNonBlocking);
    cudaEvent_t evG[NF_], evF[NF_];
    for (int j = 0; j < NF_; j++) {
        cudaEventCreateWithFlags(&evG[j], cudaEventDisableTiming);
        cudaEventCreateWithFlags(&evF[j], cudaEventDisableTiming);
    }

    // 1) split weights (all 8 flows) into bf16 hi/lo           [launch 1]
    {
        size_t n4 = (size_t)NF_ * LL2 / 4;
        split_w_kernel<<<(unsigned)((n4 + 255) / 256), 256>>>(W0, Ws, Whi, Wlo);
    }
    // 2) split h_last into X buffer 0                          [launch 2]
    {
        size_t n4 = BL / 4;
        split_x_kernel<<<(unsigned)((n4 + 255) / 256), 256>>>(h_last, Xhi, Xlo);
    }
    // 3) keep ncu's -s 5 -c 1 window on hf_gemm                [launch 3]
    dummy_shift<<<1, 32>>>();

    // 4) z -> out (flows update in place)
    cudaMemcpyAsync(out, z, BL * sizeof(float), cudaMemcpyDeviceToDevice);

    // 5) chain: GEMMs back-to-back on stream 0; flows on s2 hidden under the
    //    next GEMM. flow_j reads X buf (j+1)&1 (also read by gemm_{j+1}) and
    //    writes only `out`; gemm_{j+2} rewrites buf (j+1)&1 so it waits evF[j].
    dim3 ggrid(B_ / 128, L_ / 128, 1);  // (64, 16) = 1024 CTAs
    for (int j = 0; j < NF_; j++) {
        const int sb = j & 1;
        const int db = (j + 1) & 1;
        const float* bias = (j == 0) ? b0 : (bs + (size_t)(j - 1) * L_);
        if (j >= 2) cudaStreamWaitEvent(0, evF[j - 2], 0);   // WAR on X buf
        hf_gemm<<<ggrid, 256, GEMM_SMEM>>>(
            Xhi + (size_t)sb * BL, Xlo + (size_t)sb * BL,
            Whi + (size_t)j * LL2, Wlo + (size_t)j * LL2,
            bias,
            Xhi + (size_t)db * BL, Xlo + (size_t)db * BL);
        cudaEventRecord(evG[j], 0);
        cudaStreamWaitEvent(s2, evG[j], 0);
        hf_flow<<<B_, 256, 0, s2>>>(Xhi + (size_t)db * BL, Xlo + (size_t)db * BL, out);
        cudaEventRecord(evF[j], s2);
    }
    // join: main stream waits for final flow so capture ends fully joined
    cudaStreamWaitEvent(0, evF[NF_ - 1], 0);

    for (int j = 0; j < NF_; j++) {
        cudaEventDestroy(evG[j]);
        cudaEventDestroy(evF[j]);
    }
    cudaStreamDestroy(s2);
}